// round 9
// baseline (speedup 1.0000x reference)
#include <cuda_runtime.h>
#include <math.h>

#define Nn 16384
#define Ee 262144
#define Tt 5
#define Ff 75
#define TF 375
#define PSTR 384
#define AGGW 1500       // Tt*300  [node][tower][mean|mn|mx|std]
#define NGR 256
#define AVG_DEG_LOG 2.8332133440562162f
typedef unsigned long long ull;

// ---------------- static scratch ----------------
static __device__ float d_h[Nn*Ff];
static __device__ float d_hpre[Nn*Ff];
static __device__ float d_A[Nn*PSTR];       // pads [375..383] stay zero
static __device__ float d_Bm[Nn*PSTR];      // pads stay zero
static __device__ float d_AGG[(size_t)Nn*AGGW];
static __device__ float d_R[(size_t)Nn*240];
static __device__ float d_amp[Nn];
static __device__ int   d_off[Nn+1];
static __device__ int   d_cur[Nn];
static __device__ int   d_edges[Ee];
static __device__ float d_Ctab[16*TF];
static __device__ float d_W2[4*75*768];
static __device__ float d_QW3[4*5*300*48];
static __device__ float d_bnp1[256*Ff];
static __device__ float d_bnp2[256*Ff];
static __device__ float d_scale[Ff];
static __device__ float d_shift[Ff];

// ---------------- f32x2 helpers ----------------
__device__ __forceinline__ ull fdup(float v){
    ull r; unsigned u = __float_as_uint(v);
    asm("mov.b64 %0, {%1,%1};" : "=l"(r) : "r"(u));
    return r;
}
__device__ __forceinline__ float2 upk(ull v){
    unsigned lo, hi;
    asm("mov.b64 {%0,%1}, %2;" : "=r"(lo), "=r"(hi) : "l"(v));
    return make_float2(__uint_as_float(lo), __uint_as_float(hi));
}
__device__ __forceinline__ ull padd(ull a, ull b){
    ull r; asm("add.rn.f32x2 %0, %1, %2;" : "=l"(r) : "l"(a), "l"(b));
    return r;
}
#define FFMA2(d,a,b) asm("fma.rn.f32x2 %0, %1, %2, %0;" : "+l"(d) : "l"(a), "l"(b))

// ---------------- precompute ----------------
__global__ void k_inith(const int* __restrict__ x, const float* __restrict__ nemb){
    int i = blockIdx.x*blockDim.x + threadIdx.x;
    if (i < Nn) d_cur[i] = 0;
    if (i >= Nn*Ff) return;
    int n = i / Ff, c = i - n*Ff;
    d_h[i] = nemb[x[n]*Ff + c];
}

__global__ void k_repack(const float* __restrict__ pw, const float* __restrict__ qw){
    int i = blockIdx.x*256 + threadIdx.x;
    if (blockIdx.y == 0){
        if (i < 4*75*768){
            int l = i / (75*768); int r = i - l*(75*768);
            int c = r / 768;      int j = r - c*768;
            float v = 0.f;
            if (j < 750){
                int isB = (j >= 375); int jj = isB ? j-375 : j;
                int t = jj/75, g = jj - t*75;
                v = pw[(((l*5 + t)*225) + (isB?75:0) + c)*75 + g];
            }
            d_W2[i] = v;
        }
    } else {
        if (i < 4*5*300*48){
            int l = i / (5*300*48); int r = i - l*(5*300*48);
            int t = r / (300*48);   r -= t*(300*48);
            int k = r / 48;         int j = r - k*48;
            float v = 0.f;
            if (j < 45){
                int part = j/15, g = j - part*15;
                v = qw[((l*5+t)*900 + part*300 + k)*15 + g];
            }
            d_QW3[i] = v;
        }
    }
}

__global__ void k_hist(const int* __restrict__ dst){
    int e = blockIdx.x*blockDim.x + threadIdx.x;
    if (e < Ee) atomicAdd(&d_cur[dst[e]], 1);
}

__global__ void k_scan(){   // 1 block, 1024 threads, 16 nodes each; also amp
    __shared__ int part[1024];
    int t = threadIdx.x;
    int loc[16]; int s = 0;
    #pragma unroll
    for (int i = 0; i < 16; i++){ loc[i] = d_cur[t*16+i]; s += loc[i]; }
    part[t] = s;
    __syncthreads();
    for (int d = 1; d < 1024; d <<= 1){
        int v = (t >= d) ? part[t-d] : 0;
        __syncthreads();
        part[t] += v;
        __syncthreads();
    }
    int run = part[t] - s;
    #pragma unroll
    for (int i = 0; i < 16; i++){
        d_off[t*16+i] = run;
        d_cur[t*16+i] = run;
        float cf = (float)(loc[i] > 0 ? loc[i] : 1);
        d_amp[t*16+i] = logf(cf + 1.0f) / AVG_DEG_LOG;
        run += loc[i];
    }
    if (t == 1023) d_off[Nn] = run;
}

__global__ void k_scatter(const int* __restrict__ src, const int* __restrict__ dst,
                          const int* __restrict__ attr){
    int e = blockIdx.x*blockDim.x + threadIdx.x;
    if (e >= Ee) return;
    int d = dst[e];
    int pos = atomicAdd(&d_cur[d], 1);
    d_edges[pos] = src[e] | (attr[e] << 16);
}

// canonical per-segment order; local-memory insertion sort (fallback for long segs)
__global__ void k_sort(){
    int n = blockIdx.x*blockDim.x + threadIdx.x;
    if (n >= Nn) return;
    int lo = d_off[n];
    int m = d_off[n+1] - lo;
    if (m <= 72){
        int a[72];
        for (int i = 0; i < m; i++) a[i] = d_edges[lo+i];
        for (int i = 1; i < m; i++){
            int key = a[i]; int j = i-1;
            while (j >= 0 && a[j] > key){ a[j+1] = a[j]; j--; }
            a[j+1] = key;
        }
        for (int i = 0; i < m; i++) d_edges[lo+i] = a[i];
    } else {
        for (int i = 1; i < m; i++){
            int key = d_edges[lo+i]; int j = i-1;
            while (j >= 0 && d_edges[lo+j] > key){ d_edges[lo+j+1] = d_edges[lo+j]; j--; }
            d_edges[lo+j+1] = key;
        }
    }
}

__global__ void k_ctab(const float* __restrict__ eemb, const float* __restrict__ eew,
                       const float* __restrict__ eeb,  const float* __restrict__ pw){
    int l = blockIdx.x >> 2, a = blockIdx.x & 3;
    __shared__ float ee[Ff];
    int tid = threadIdx.x;
    for (int f = tid; f < Ff; f += blockDim.x){
        float s = eeb[l*Ff + f];
        for (int d0 = 0; d0 < 50; d0++)
            s = fmaf(eemb[a*50 + d0], eew[(l*50 + d0)*Ff + f], s);
        ee[f] = s;
    }
    __syncthreads();
    for (int j = tid; j < TF; j += blockDim.x){
        int t = j / Ff, g = j - t*Ff;
        const float* w = pw + ((size_t)(l*Tt + t))*225*Ff + 150*Ff + g;
        float s = 0.f;
        for (int f = 0; f < Ff; f++) s = fmaf(ee[f], w[f*Ff], s);
        d_Ctab[(l*4 + a)*TF + j] = s;
    }
}

// ---------------- k_pre: GEMM tile 64n x 128j, node-paired f32x2 (verified) ----------------
__global__ __launch_bounds__(256, 4) void k_pre(int l, const float* __restrict__ PB){
    __shared__ float Hs[75*68];   // [c][nn], stride 68
    __shared__ float Ws[25*128];
    int tid = threadIdx.x;
    int tx = tid & 31, ty = tid >> 5;
    int n0 = blockIdx.x * 64;
    int chunk = blockIdx.y;       // 0..5
    const float* w2p = d_W2 + l*75*768 + chunk*128;

    for (int i = tid; i < 64*75; i += 256){
        int nn = i / 75, c = i - nn*75;
        float v;
        if (l == 0) v = d_h[(n0+nn)*Ff + c];
        else        v = fmaxf(fmaf(d_hpre[(n0+nn)*Ff + c], d_scale[c], d_shift[c]), 0.f);
        Hs[c*68 + nn] = v;
    }

    ull acc[4][4];
    #pragma unroll
    for (int m = 0; m < 4; m++)
        #pragma unroll
        for (int p = 0; p < 4; p++) acc[m][p] = 0ull;

    for (int s = 0; s < 3; s++){
        int c0 = s*25;
        __syncthreads();
        for (int i = tid; i < 25*128; i += 256){
            int kk = i >> 7, j = i & 127;
            Ws[i] = w2p[(c0+kk)*768 + j];
        }
        __syncthreads();
        #pragma unroll 5
        for (int kk = 0; kk < 25; kk++){
            const float* hr = &Hs[(c0+kk)*68 + ty*8];
            ulonglong2 h01 = *(const ulonglong2*)(hr);
            ulonglong2 h23 = *(const ulonglong2*)(hr+4);
            ull hv[4] = {h01.x, h01.y, h23.x, h23.y};
            float4 wf = *(const float4*)&Ws[kk*128 + tx*4];
            ull wd0 = fdup(wf.x), wd1 = fdup(wf.y), wd2 = fdup(wf.z), wd3 = fdup(wf.w);
            #pragma unroll
            for (int m = 0; m < 4; m++){
                FFMA2(acc[m][0], hv[m], wd0);
                FFMA2(acc[m][1], hv[m], wd1);
                FFMA2(acc[m][2], hv[m], wd2);
                FFMA2(acc[m][3], hv[m], wd3);
            }
        }
    }

    int jbase = chunk*128 + tx*4;
    #pragma unroll
    for (int m = 0; m < 4; m++){
        int na = n0 + ty*8 + 2*m;
        int nb = na + 1;
        #pragma unroll
        for (int p = 0; p < 4; p++){
            float2 v = upk(acc[m][p]);
            int j = jbase + p;
            if (j < 375){
                float bias = PB[j];
                d_A[na*PSTR + j] = v.x + bias;
                d_A[nb*PSTR + j] = v.y + bias;
            } else if (j < 750){
                int jb = j - 375;
                d_Bm[na*PSTR + jb] = v.x;
                d_Bm[nb*PSTR + jb] = v.y;
            }
        }
    }
}

// ---------------- k_agg: 3 warps/node, 2-way pipelined edge chains ----------------
__global__ __launch_bounds__(256) void k_agg(int l){
    __shared__ float ct[4*384];
    int tid = threadIdx.x;
    const float* cl = d_Ctab + l*4*TF;
    for (int i = tid; i < 4*384; i += 256){
        int a = i / 384, f = i - a*384;
        ct[i] = (f < 375) ? cl[a*375 + f] : 0.f;
    }
    __syncthreads();
    int gw = (blockIdx.x*256 + tid) >> 5;   // grid = Nn*3/8 blocks -> gw < Nn*3
    int node = gw / 3;
    int third = gw - node*3;
    int lane = tid & 31;
    int fbase = third*128 + lane*4;
    int o0 = d_off[node], o1 = d_off[node+1];

    // chain A
    ull sA0 = 0, sA1 = 0, qA0 = 0, qA1 = 0;
    float mnA0 = 3.4e38f, mnA1 = 3.4e38f, mnA2 = 3.4e38f, mnA3 = 3.4e38f;
    float mxA0 = -3.4e38f, mxA1 = -3.4e38f, mxA2 = -3.4e38f, mxA3 = -3.4e38f;
    // chain B
    ull sB0 = 0, sB1 = 0, qB0 = 0, qB1 = 0;
    float mnB0 = 3.4e38f, mnB1 = 3.4e38f, mnB2 = 3.4e38f, mnB3 = 3.4e38f;
    float mxB0 = -3.4e38f, mxB1 = -3.4e38f, mxB2 = -3.4e38f, mxB3 = -3.4e38f;

    int i = o0;
    for (; i + 1 < o1; i += 2){
        int pa = d_edges[i];
        int pb = d_edges[i+1];
        ulonglong2 ba = *(const ulonglong2*)(d_Bm + (pa & 0xFFFF)*PSTR + fbase);
        ulonglong2 bb = *(const ulonglong2*)(d_Bm + (pb & 0xFFFF)*PSTR + fbase);
        ulonglong2 ca = *(const ulonglong2*)(ct + (pa >> 16)*384 + fbase);
        ulonglong2 cb = *(const ulonglong2*)(ct + (pb >> 16)*384 + fbase);
        ull va0 = padd(ba.x, ca.x), va1 = padd(ba.y, ca.y);
        ull vb0 = padd(bb.x, cb.x), vb1 = padd(bb.y, cb.y);
        sA0 = padd(sA0, va0); sA1 = padd(sA1, va1);
        sB0 = padd(sB0, vb0); sB1 = padd(sB1, vb1);
        FFMA2(qA0, va0, va0); FFMA2(qA1, va1, va1);
        FFMA2(qB0, vb0, vb0); FFMA2(qB1, vb1, vb1);
        float2 fa0 = upk(va0), fa1 = upk(va1);
        float2 fb0 = upk(vb0), fb1 = upk(vb1);
        mnA0 = fminf(mnA0, fa0.x); mxA0 = fmaxf(mxA0, fa0.x);
        mnA1 = fminf(mnA1, fa0.y); mxA1 = fmaxf(mxA1, fa0.y);
        mnA2 = fminf(mnA2, fa1.x); mxA2 = fmaxf(mxA2, fa1.x);
        mnA3 = fminf(mnA3, fa1.y); mxA3 = fmaxf(mxA3, fa1.y);
        mnB0 = fminf(mnB0, fb0.x); mxB0 = fmaxf(mxB0, fb0.x);
        mnB1 = fminf(mnB1, fb0.y); mxB1 = fmaxf(mxB1, fb0.y);
        mnB2 = fminf(mnB2, fb1.x); mxB2 = fmaxf(mxB2, fb1.x);
        mnB3 = fminf(mnB3, fb1.y); mxB3 = fmaxf(mxB3, fb1.y);
    }
    if (i < o1){   // odd tail -> chain A
        int pa = d_edges[i];
        ulonglong2 ba = *(const ulonglong2*)(d_Bm + (pa & 0xFFFF)*PSTR + fbase);
        ulonglong2 ca = *(const ulonglong2*)(ct + (pa >> 16)*384 + fbase);
        ull va0 = padd(ba.x, ca.x), va1 = padd(ba.y, ca.y);
        sA0 = padd(sA0, va0); sA1 = padd(sA1, va1);
        FFMA2(qA0, va0, va0); FFMA2(qA1, va1, va1);
        float2 fa0 = upk(va0), fa1 = upk(va1);
        mnA0 = fminf(mnA0, fa0.x); mxA0 = fmaxf(mxA0, fa0.x);
        mnA1 = fminf(mnA1, fa0.y); mxA1 = fmaxf(mxA1, fa0.y);
        mnA2 = fminf(mnA2, fa1.x); mxA2 = fmaxf(mxA2, fa1.x);
        mnA3 = fminf(mnA3, fa1.y); mxA3 = fmaxf(mxA3, fa1.y);
    }
    // merge chains (fixed order -> deterministic)
    ull sum0 = padd(sA0, sB0), sum1 = padd(sA1, sB1);
    ull sq0  = padd(qA0, qB0), sq1  = padd(qA1, qB1);
    float nv[4] = { fminf(mnA0,mnB0), fminf(mnA1,mnB1), fminf(mnA2,mnB2), fminf(mnA3,mnB3) };
    float xv[4] = { fmaxf(mxA0,mxB0), fmaxf(mxA1,mxB1), fmaxf(mxA2,mxB2), fmaxf(mxA3,mxB3) };

    int cnt = o1 - o0;
    float inv = 1.0f / (float)(cnt > 0 ? cnt : 1);
    bool has = cnt > 0;
    float* aggb = d_AGG + (size_t)node*AGGW;
    float4 a4 = *(const float4*)(d_A + node*PSTR + fbase);
    float2 s0 = upk(sum0), s1 = upk(sum1);
    float2 q0 = upk(sq0),  q1 = upk(sq1);
    float av[4] = {a4.x, a4.y, a4.z, a4.w};
    float sv[4] = {s0.x, s0.y, s1.x, s1.y};
    float qv[4] = {q0.x, q0.y, q1.x, q1.y};
    #pragma unroll
    for (int e = 0; e < 4; e++){
        int f = fbase + e;
        if (f < 375){
            float mp  = sv[e]*inv;
            float var = fmaf(-mp, mp, qv[e]*inv);
            float sd  = sqrtf(fmaxf(var, 0.f) + 1e-5f);
            float a   = av[e];
            int t = f/75, ff = f - t*75;
            float* dp = aggb + t*300 + ff;
            dp[0]   = has ? a + mp    : 0.f;
            dp[75]  = has ? a + nv[e] : 0.f;
            dp[150] = has ? a + xv[e] : 0.f;
            dp[225] = sd;
        }
    }
}

// ---------------- k_post2: per-tower GEMM [128n x 48] x [300k] (verified) ----------------
__global__ __launch_bounds__(256, 4) void k_post2(int l){
    __shared__ float Ag[20*260];   // dup nodes: [kk][2*128 + pad]
    __shared__ float Ws[20*48];
    int tid = threadIdx.x;
    int tx = tid & 7, ty = tid >> 3;
    int n0 = blockIdx.x * 128;
    int t  = blockIdx.y;
    const float* qwp = d_QW3 + (size_t)(l*5 + t)*300*48;

    ull acc[4][3];
    #pragma unroll
    for (int n = 0; n < 4; n++)
        #pragma unroll
        for (int p = 0; p < 3; p++) acc[n][p] = 0ull;

    for (int s = 0; s < 15; s++){
        int k0 = s*20;
        __syncthreads();
        for (int i = tid; i < 128*20; i += 256){
            int nn = i / 20, kk = i - nn*20;
            float v = d_AGG[(size_t)(n0+nn)*AGGW + t*300 + k0 + kk];
            *(ull*)&Ag[kk*260 + 2*nn] = fdup(v);
        }
        for (int i = tid; i < 20*48; i += 256){
            int kk = i / 48, j = i - kk*48;
            Ws[i] = qwp[(k0 + kk)*48 + j];
        }
        __syncthreads();
        #pragma unroll 5
        for (int kk = 0; kk < 20; kk++){
            const float* hr = &Ag[kk*260 + ty*8];
            ulonglong2 q0 = *(const ulonglong2*)(hr);
            ulonglong2 q1 = *(const ulonglong2*)(hr+4);
            ull hv[4] = {q0.x, q0.y, q1.x, q1.y};
            const float* wr = &Ws[kk*48 + tx*6];
            ull wv[3];
            wv[0] = *(const ull*)(wr);
            wv[1] = *(const ull*)(wr+2);
            wv[2] = *(const ull*)(wr+4);
            #pragma unroll
            for (int n = 0; n < 4; n++)
                #pragma unroll
                for (int p = 0; p < 3; p++)
                    FFMA2(acc[n][p], hv[n], wv[p]);
        }
    }
    #pragma unroll
    for (int n = 0; n < 4; n++){
        int node = n0 + ty*4 + n;
        ull* dst = (ull*)&d_R[(size_t)node*240 + t*48 + tx*6];
        dst[0] = acc[n][0]; dst[1] = acc[n][1]; dst[2] = acc[n][2];
    }
}

// ---------------- k_lin: combine(amp) + 75x75 GEMM + BN partials ----------------
__global__ void k_lin(const float* __restrict__ QB, const float* __restrict__ LW,
                      const float* __restrict__ LB){
    extern __shared__ float sm[];
    float* post = sm;            // 64*76
    float* LWs  = sm + 4864;     // 75*76
    float* outs = sm + 4864 + 5700;  // 64*76
    float* s_amp  = sm + 4864 + 5700 + 4864;
    float* s_ampi = s_amp + 64;
    int tid = threadIdx.x;
    int n0 = blockIdx.x * 64;
    if (tid < 64){
        float a = d_amp[n0 + tid];
        s_amp[tid] = a; s_ampi[tid] = 1.0f / a;
    }
    for (int i = tid; i < 75*75; i += 256){
        int k = i / 75, j = i - k*75;
        LWs[k*76 + j] = LW[i];
    }
    __syncthreads();
    for (int i = tid; i < 64*75; i += 256){
        int nn = i / 75, j = i - nn*75;
        int t = j / 15, g = j - t*15;
        const float* rp = d_R + (size_t)(n0+nn)*240 + t*48;
        float r1 = rp[g], r2 = rp[15+g], r3 = rp[30+g];
        post[nn*76 + j] = r1 + s_amp[nn]*r2 + s_ampi[nn]*r3 + QB[j];
    }
    __syncthreads();
    if (tid < 240){
        int q = tid / 15, g5 = tid - q*15;
        int j0 = g5*5;
        float acc[4][5];
        #pragma unroll
        for (int i = 0; i < 4; i++)
            #pragma unroll
            for (int c = 0; c < 5; c++) acc[i][c] = LB[j0+c];
        for (int k = 0; k < 75; k++){
            float pv[4];
            #pragma unroll
            for (int i = 0; i < 4; i++) pv[i] = post[(q*4+i)*76 + k];
            #pragma unroll
            for (int c = 0; c < 5; c++){
                float wv = LWs[k*76 + j0 + c];
                #pragma unroll
                for (int i = 0; i < 4; i++) acc[i][c] = fmaf(pv[i], wv, acc[i][c]);
            }
        }
        #pragma unroll
        for (int i = 0; i < 4; i++){
            int nn = q*4 + i;
            #pragma unroll
            for (int c = 0; c < 5; c++){
                outs[nn*76 + j0 + c] = acc[i][c];
                d_hpre[(n0+nn)*Ff + j0 + c] = acc[i][c];
            }
        }
    }
    __syncthreads();
    if (tid < 75){
        float s = 0.f, s2 = 0.f;
        for (int nn = 0; nn < 64; nn++){
            float v = outs[nn*76 + tid];
            s += v; s2 = fmaf(v, v, s2);
        }
        d_bnp1[blockIdx.x*Ff + tid] = s;
        d_bnp2[blockIdx.x*Ff + tid] = s2;
    }
}

// grid 75, block 256: parallel deterministic tree reduction of BN partials
__global__ void k_bnred(const float* __restrict__ gamma, const float* __restrict__ beta){
    __shared__ float s1[256], s2[256];
    int j = blockIdx.x, t = threadIdx.x;
    s1[t] = d_bnp1[t*Ff + j];
    s2[t] = d_bnp2[t*Ff + j];
    __syncthreads();
    for (int d = 128; d > 0; d >>= 1){
        if (t < d){ s1[t] += s1[t+d]; s2[t] += s2[t+d]; }
        __syncthreads();
    }
    if (t == 0){
        float mu  = s1[0] / (float)Nn;
        float var = s2[0] / (float)Nn - mu*mu;
        var = fmaxf(var, 0.f);
        float sc = gamma[j] * rsqrtf(var + 1e-5f);
        d_scale[j] = sc;
        d_shift[j] = beta[j] - mu*sc;
    }
}

// ---------------- fused readout ----------------
__global__ void k_read(const int* __restrict__ batch,
                       const float* __restrict__ w1, const float* __restrict__ b1,
                       const float* __restrict__ w2, const float* __restrict__ b2,
                       const float* __restrict__ w3, const float* __restrict__ b3,
                       float* __restrict__ out){
    __shared__ float gv[Ff], h1[50], h2[25];
    __shared__ int bounds[2];
    int g = blockIdx.x, tid = threadIdx.x;
    if (tid < 2){
        int target = g + tid;
        int lo = 0, hi = Nn;
        while (lo < hi){ int mid = (lo+hi) >> 1; if (batch[mid] < target) lo = mid+1; else hi = mid; }
        bounds[tid] = lo;
    }
    __syncthreads();
    int a = bounds[0], b = bounds[1];
    for (int j = tid; j < Ff; j += blockDim.x){
        float sc = d_scale[j], sh = d_shift[j];
        float s = 0.f;
        for (int n = a; n < b; n++)
            s += fmaxf(fmaf(d_hpre[n*Ff + j], sc, sh), 0.f);
        gv[j] = s;
    }
    __syncthreads();
    if (tid < 50){
        float s = b1[tid];
        for (int k = 0; k < Ff; k++) s = fmaf(gv[k], w1[k*50 + tid], s);
        h1[tid] = fmaxf(s, 0.f);
    }
    __syncthreads();
    if (tid < 25){
        float s = b2[tid];
        for (int k = 0; k < 50; k++) s = fmaf(h1[k], w2[k*25 + tid], s);
        h2[tid] = fmaxf(s, 0.f);
    }
    __syncthreads();
    if (tid == 0){
        float s = b3[0];
        for (int k = 0; k < 25; k++) s = fmaf(h2[k], w3[k], s);
        out[g] = s;
    }
}

// ---------------- launch ----------------
extern "C" void kernel_launch(void* const* d_in, const int* in_sizes, int n_in,
                              void* d_out, int out_size){
    const int*   x     = (const int*)  d_in[0];
    const int*   ei    = (const int*)  d_in[1];
    const int*   eattr = (const int*)  d_in[2];
    const int*   batch = (const int*)  d_in[3];
    const float* nemb  = (const float*)d_in[4];
    const float* eemb  = (const float*)d_in[5];
    const float* eew   = (const float*)d_in[6];
    const float* eeb   = (const float*)d_in[7];
    const float* pw    = (const float*)d_in[8];
    const float* pb    = (const float*)d_in[9];
    const float* qw    = (const float*)d_in[10];
    const float* qb    = (const float*)d_in[11];
    const float* lw    = (const float*)d_in[12];
    const float* lb    = (const float*)d_in[13];
    const float* bng   = (const float*)d_in[14];
    const float* bnb   = (const float*)d_in[15];
    const float* w1    = (const float*)d_in[16];
    const float* b1    = (const float*)d_in[17];
    const float* w2    = (const float*)d_in[18];
    const float* b2    = (const float*)d_in[19];
    const float* w3    = (const float*)d_in[20];
    const float* b3    = (const float*)d_in[21];
    float* out = (float*)d_out;
    const int* src = ei;
    const int* dst = ei + Ee;

    cudaFuncSetAttribute(k_lin, cudaFuncAttributeMaxDynamicSharedMemorySize, 62464);

    k_inith<<<(Nn*Ff+255)/256,256>>>(x, nemb);                    // 1 (also zeroes d_cur)
    k_repack<<<dim3(1125,2),256>>>(pw, qw);                       // 2
    k_hist<<<Ee/256,256>>>(dst);                                  // 3
    // 4: SACRIFICIAL k_agg for profiling. Reads steady-state d_off/d_edges/d_Ctab/d_Bm
    // from the previous replay (identical every replay); its d_AGG output is fully
    // overwritten by the real k_agg(0) below. First call: d_off==0 -> empty loops.
    k_agg<<<Nn*3/8,256>>>(0);                                     // 4 <- profiled slot
    k_pre<<<dim3(Nn/64,6),256>>>(0, pb);                          // 5
    k_scan<<<1,1024>>>();                                         // 6
    k_scatter<<<Ee/256,256>>>(src, dst, eattr);                   // 7
    k_sort<<<64,256>>>();                                         // 8
    k_ctab<<<16,128>>>(eemb, eew, eeb, pw);                       // 9

    for (int l = 0; l < 4; l++){
        if (l > 0)
            k_pre<<<dim3(Nn/64,6),256>>>(l, pb + l*TF);
        k_agg<<<Nn*3/8,256>>>(l);
        k_post2<<<dim3(Nn/128,5),256>>>(l);
        k_lin<<<Nn/64,256,62464>>>(qb + l*Ff, lw + l*Ff*Ff, lb + l*Ff);
        k_bnred<<<75,256>>>(bng + l*Ff, bnb + l*Ff);
    }

    k_read<<<NGR,128>>>(batch, w1, b1, w2, b2, w3, b3, out);
}

// round 10
// speedup vs baseline: 1.0085x; 1.0085x over previous
#include <cuda_runtime.h>
#include <math.h>

#define Nn 16384
#define Ee 262144
#define Tt 5
#define Ff 75
#define TF 375
#define PSTR 384
#define AGGW 1500       // Tt*300  [node][tower][mean|mn|mx|std]
#define NGR 256
#define AVG_DEG_LOG 2.8332133440562162f
typedef unsigned long long ull;

// ---------------- static scratch ----------------
static __device__ float d_h[Nn*Ff];
static __device__ float d_hpre[Nn*Ff];
static __device__ float d_A[Nn*PSTR];       // pads [375..383] stay zero
static __device__ float d_Bm[Nn*PSTR];      // pads stay zero
static __device__ float d_AGG[(size_t)Nn*AGGW];
static __device__ float d_R[(size_t)Nn*240];
static __device__ float d_amp[Nn];
static __device__ int   d_off[Nn+1];
static __device__ int   d_cur[Nn];
static __device__ int   d_edges[Ee];
static __device__ float d_Ctab[16*TF];
static __device__ float d_W2[4*75*768];
static __device__ float d_QW3[4*5*300*48];
static __device__ float d_bnp1[256*Ff];
static __device__ float d_bnp2[256*Ff];
static __device__ float d_scale[Ff];
static __device__ float d_shift[Ff];

// ---------------- f32x2 helpers ----------------
__device__ __forceinline__ ull fdup(float v){
    ull r; unsigned u = __float_as_uint(v);
    asm("mov.b64 %0, {%1,%1};" : "=l"(r) : "r"(u));
    return r;
}
__device__ __forceinline__ float2 upk(ull v){
    unsigned lo, hi;
    asm("mov.b64 {%0,%1}, %2;" : "=r"(lo), "=r"(hi) : "l"(v));
    return make_float2(__uint_as_float(lo), __uint_as_float(hi));
}
__device__ __forceinline__ ull padd(ull a, ull b){
    ull r; asm("add.rn.f32x2 %0, %1, %2;" : "=l"(r) : "l"(a), "l"(b));
    return r;
}
#define FFMA2(d,a,b) asm("fma.rn.f32x2 %0, %1, %2, %0;" : "+l"(d) : "l"(a), "l"(b))

// ---------------- precompute ----------------
__global__ void k_inith(const int* __restrict__ x, const float* __restrict__ nemb){
    int i = blockIdx.x*blockDim.x + threadIdx.x;
    if (i < Nn) d_cur[i] = 0;
    if (i >= Nn*Ff) return;
    int n = i / Ff, c = i - n*Ff;
    d_h[i] = nemb[x[n]*Ff + c];
}

__global__ void k_repack(const float* __restrict__ pw, const float* __restrict__ qw){
    int i = blockIdx.x*256 + threadIdx.x;
    if (blockIdx.y == 0){
        if (i < 4*75*768){
            int l = i / (75*768); int r = i - l*(75*768);
            int c = r / 768;      int j = r - c*768;
            float v = 0.f;
            if (j < 750){
                int isB = (j >= 375); int jj = isB ? j-375 : j;
                int t = jj/75, g = jj - t*75;
                v = pw[(((l*5 + t)*225) + (isB?75:0) + c)*75 + g];
            }
            d_W2[i] = v;
        }
    } else {
        if (i < 4*5*300*48){
            int l = i / (5*300*48); int r = i - l*(5*300*48);
            int t = r / (300*48);   r -= t*(300*48);
            int k = r / 48;         int j = r - k*48;
            float v = 0.f;
            if (j < 45){
                int part = j/15, g = j - part*15;
                v = qw[((l*5+t)*900 + part*300 + k)*15 + g];
            }
            d_QW3[i] = v;
        }
    }
}

__global__ void k_hist(const int* __restrict__ dst){
    int e = blockIdx.x*blockDim.x + threadIdx.x;
    if (e < Ee) atomicAdd(&d_cur[dst[e]], 1);
}

__global__ void k_scan(){   // 1 block, 1024 threads, 16 nodes each; also amp
    __shared__ int part[1024];
    int t = threadIdx.x;
    int loc[16]; int s = 0;
    #pragma unroll
    for (int i = 0; i < 16; i++){ loc[i] = d_cur[t*16+i]; s += loc[i]; }
    part[t] = s;
    __syncthreads();
    for (int d = 1; d < 1024; d <<= 1){
        int v = (t >= d) ? part[t-d] : 0;
        __syncthreads();
        part[t] += v;
        __syncthreads();
    }
    int run = part[t] - s;
    #pragma unroll
    for (int i = 0; i < 16; i++){
        d_off[t*16+i] = run;
        d_cur[t*16+i] = run;
        float cf = (float)(loc[i] > 0 ? loc[i] : 1);
        d_amp[t*16+i] = logf(cf + 1.0f) / AVG_DEG_LOG;
        run += loc[i];
    }
    if (t == 1023) d_off[Nn] = run;
}

__global__ void k_scatter(const int* __restrict__ src, const int* __restrict__ dst,
                          const int* __restrict__ attr){
    int e = blockIdx.x*blockDim.x + threadIdx.x;
    if (e >= Ee) return;
    int d = dst[e];
    int pos = atomicAdd(&d_cur[d], 1);
    d_edges[pos] = src[e] | (attr[e] << 16);
}

// canonical per-segment order; local-memory insertion sort (fallback for long segs)
__global__ void k_sort(){
    int n = blockIdx.x*blockDim.x + threadIdx.x;
    if (n >= Nn) return;
    int lo = d_off[n];
    int m = d_off[n+1] - lo;
    if (m <= 72){
        int a[72];
        for (int i = 0; i < m; i++) a[i] = d_edges[lo+i];
        for (int i = 1; i < m; i++){
            int key = a[i]; int j = i-1;
            while (j >= 0 && a[j] > key){ a[j+1] = a[j]; j--; }
            a[j+1] = key;
        }
        for (int i = 0; i < m; i++) d_edges[lo+i] = a[i];
    } else {
        for (int i = 1; i < m; i++){
            int key = d_edges[lo+i]; int j = i-1;
            while (j >= 0 && d_edges[lo+j] > key){ d_edges[lo+j+1] = d_edges[lo+j]; j--; }
            d_edges[lo+j+1] = key;
        }
    }
}

__global__ void k_ctab(const float* __restrict__ eemb, const float* __restrict__ eew,
                       const float* __restrict__ eeb,  const float* __restrict__ pw){
    int l = blockIdx.x >> 2, a = blockIdx.x & 3;
    __shared__ float ee[Ff];
    int tid = threadIdx.x;
    for (int f = tid; f < Ff; f += blockDim.x){
        float s = eeb[l*Ff + f];
        for (int d0 = 0; d0 < 50; d0++)
            s = fmaf(eemb[a*50 + d0], eew[(l*50 + d0)*Ff + f], s);
        ee[f] = s;
    }
    __syncthreads();
    for (int j = tid; j < TF; j += blockDim.x){
        int t = j / Ff, g = j - t*Ff;
        const float* w = pw + ((size_t)(l*Tt + t))*225*Ff + 150*Ff + g;
        float s = 0.f;
        for (int f = 0; f < Ff; f++) s = fmaf(ee[f], w[f*Ff], s);
        d_Ctab[(l*4 + a)*TF + j] = s;
    }
}

// ---------------- k_pre: GEMM tile 64n x 128j, node-paired f32x2 (verified) ----------------
__global__ __launch_bounds__(256, 4) void k_pre(int l, const float* __restrict__ PB){
    __shared__ float Hs[75*68];   // [c][nn], stride 68
    __shared__ float Ws[25*128];
    int tid = threadIdx.x;
    int tx = tid & 31, ty = tid >> 5;
    int n0 = blockIdx.x * 64;
    int chunk = blockIdx.y;       // 0..5
    const float* w2p = d_W2 + l*75*768 + chunk*128;

    for (int i = tid; i < 64*75; i += 256){
        int nn = i / 75, c = i - nn*75;
        float v;
        if (l == 0) v = d_h[(n0+nn)*Ff + c];
        else        v = fmaxf(fmaf(d_hpre[(n0+nn)*Ff + c], d_scale[c], d_shift[c]), 0.f);
        Hs[c*68 + nn] = v;
    }

    ull acc[4][4];
    #pragma unroll
    for (int m = 0; m < 4; m++)
        #pragma unroll
        for (int p = 0; p < 4; p++) acc[m][p] = 0ull;

    for (int s = 0; s < 3; s++){
        int c0 = s*25;
        __syncthreads();
        for (int i = tid; i < 25*128; i += 256){
            int kk = i >> 7, j = i & 127;
            Ws[i] = w2p[(c0+kk)*768 + j];
        }
        __syncthreads();
        #pragma unroll 5
        for (int kk = 0; kk < 25; kk++){
            const float* hr = &Hs[(c0+kk)*68 + ty*8];
            ulonglong2 h01 = *(const ulonglong2*)(hr);
            ulonglong2 h23 = *(const ulonglong2*)(hr+4);
            ull hv[4] = {h01.x, h01.y, h23.x, h23.y};
            float4 wf = *(const float4*)&Ws[kk*128 + tx*4];
            ull wd0 = fdup(wf.x), wd1 = fdup(wf.y), wd2 = fdup(wf.z), wd3 = fdup(wf.w);
            #pragma unroll
            for (int m = 0; m < 4; m++){
                FFMA2(acc[m][0], hv[m], wd0);
                FFMA2(acc[m][1], hv[m], wd1);
                FFMA2(acc[m][2], hv[m], wd2);
                FFMA2(acc[m][3], hv[m], wd3);
            }
        }
    }

    int jbase = chunk*128 + tx*4;
    #pragma unroll
    for (int m = 0; m < 4; m++){
        int na = n0 + ty*8 + 2*m;
        int nb = na + 1;
        #pragma unroll
        for (int p = 0; p < 4; p++){
            float2 v = upk(acc[m][p]);
            int j = jbase + p;
            if (j < 375){
                float bias = PB[j];
                d_A[na*PSTR + j] = v.x + bias;
                d_A[nb*PSTR + j] = v.y + bias;
            } else if (j < 750){
                int jb = j - 375;
                d_Bm[na*PSTR + jb] = v.x;
                d_Bm[nb*PSTR + jb] = v.y;
            }
        }
    }
}

// ---------------- k_agg: 3 warps/node, simple chain (round-8 verified) ----------------
__global__ __launch_bounds__(256) void k_agg(int l){
    __shared__ float ct[4*384];
    int tid = threadIdx.x;
    const float* cl = d_Ctab + l*4*TF;
    for (int i = tid; i < 4*384; i += 256){
        int a = i / 384, f = i - a*384;
        ct[i] = (f < 375) ? cl[a*375 + f] : 0.f;
    }
    __syncthreads();
    int gw = (blockIdx.x*256 + tid) >> 5;   // grid = Nn*3/8 blocks -> gw < Nn*3
    int node = gw / 3;
    int third = gw - node*3;
    int lane = tid & 31;
    int fbase = third*128 + lane*4;          // float index of this lane's 4 features
    int o0 = d_off[node], o1 = d_off[node+1];

    ull sum0 = 0, sum1 = 0, sq0 = 0, sq1 = 0;
    float mn0 = 3.4e38f, mn1 = 3.4e38f, mn2 = 3.4e38f, mn3 = 3.4e38f;
    float mx0 = -3.4e38f, mx1 = -3.4e38f, mx2 = -3.4e38f, mx3 = -3.4e38f;

    for (int i = o0; i < o1; i++){
        int p = d_edges[i];
        ulonglong2 b = *(const ulonglong2*)(d_Bm + (p & 0xFFFF)*PSTR + fbase);
        ulonglong2 c = *(const ulonglong2*)(ct + (p >> 16)*384 + fbase);
        ull v0 = padd(b.x, c.x);
        ull v1 = padd(b.y, c.y);
        sum0 = padd(sum0, v0);
        sum1 = padd(sum1, v1);
        FFMA2(sq0, v0, v0);
        FFMA2(sq1, v1, v1);
        float2 f0 = upk(v0), f1 = upk(v1);
        mn0 = fminf(mn0, f0.x); mx0 = fmaxf(mx0, f0.x);
        mn1 = fminf(mn1, f0.y); mx1 = fmaxf(mx1, f0.y);
        mn2 = fminf(mn2, f1.x); mx2 = fmaxf(mx2, f1.x);
        mn3 = fminf(mn3, f1.y); mx3 = fmaxf(mx3, f1.y);
    }

    int cnt = o1 - o0;
    float inv = 1.0f / (float)(cnt > 0 ? cnt : 1);
    bool has = cnt > 0;
    float* aggb = d_AGG + (size_t)node*AGGW;
    float4 a4 = *(const float4*)(d_A + node*PSTR + fbase);
    float2 s0 = upk(sum0), s1 = upk(sum1);
    float2 q0 = upk(sq0),  q1 = upk(sq1);
    float av[4] = {a4.x, a4.y, a4.z, a4.w};
    float sv[4] = {s0.x, s0.y, s1.x, s1.y};
    float qv[4] = {q0.x, q0.y, q1.x, q1.y};
    float nv[4] = {mn0, mn1, mn2, mn3};
    float xv[4] = {mx0, mx1, mx2, mx3};
    #pragma unroll
    for (int e = 0; e < 4; e++){
        int f = fbase + e;
        if (f < 375){
            float mp  = sv[e]*inv;
            float var = fmaf(-mp, mp, qv[e]*inv);
            float sd  = sqrtf(fmaxf(var, 0.f) + 1e-5f);
            float a   = av[e];
            int t = f/75, ff = f - t*75;
            float* dp = aggb + t*300 + ff;
            dp[0]   = has ? a + mp    : 0.f;
            dp[75]  = has ? a + nv[e] : 0.f;
            dp[150] = has ? a + xv[e] : 0.f;
            dp[225] = sd;
        }
    }
}

// ---------------- k_post2: per-tower GEMM [128n x 48] x [300k] (verified) ----------------
__global__ __launch_bounds__(256, 4) void k_post2(int l){
    __shared__ float Ag[20*260];   // dup nodes: [kk][2*128 + pad]
    __shared__ float Ws[20*48];
    int tid = threadIdx.x;
    int tx = tid & 7, ty = tid >> 3;
    int n0 = blockIdx.x * 128;
    int t  = blockIdx.y;
    const float* qwp = d_QW3 + (size_t)(l*5 + t)*300*48;

    ull acc[4][3];
    #pragma unroll
    for (int n = 0; n < 4; n++)
        #pragma unroll
        for (int p = 0; p < 3; p++) acc[n][p] = 0ull;

    for (int s = 0; s < 15; s++){
        int k0 = s*20;
        __syncthreads();
        for (int i = tid; i < 128*20; i += 256){
            int nn = i / 20, kk = i - nn*20;
            float v = d_AGG[(size_t)(n0+nn)*AGGW + t*300 + k0 + kk];
            *(ull*)&Ag[kk*260 + 2*nn] = fdup(v);
        }
        for (int i = tid; i < 20*48; i += 256){
            int kk = i / 48, j = i - kk*48;
            Ws[i] = qwp[(k0 + kk)*48 + j];
        }
        __syncthreads();
        #pragma unroll 5
        for (int kk = 0; kk < 20; kk++){
            const float* hr = &Ag[kk*260 + ty*8];
            ulonglong2 q0 = *(const ulonglong2*)(hr);
            ulonglong2 q1 = *(const ulonglong2*)(hr+4);
            ull hv[4] = {q0.x, q0.y, q1.x, q1.y};
            const float* wr = &Ws[kk*48 + tx*6];
            ull wv[3];
            wv[0] = *(const ull*)(wr);
            wv[1] = *(const ull*)(wr+2);
            wv[2] = *(const ull*)(wr+4);
            #pragma unroll
            for (int n = 0; n < 4; n++)
                #pragma unroll
                for (int p = 0; p < 3; p++)
                    FFMA2(acc[n][p], hv[n], wv[p]);
        }
    }
    #pragma unroll
    for (int n = 0; n < 4; n++){
        int node = n0 + ty*4 + n;
        ull* dst = (ull*)&d_R[(size_t)node*240 + t*48 + tx*6];
        dst[0] = acc[n][0]; dst[1] = acc[n][1]; dst[2] = acc[n][2];
    }
}

// ---------------- k_lin: combine(amp) + 75x75 GEMM + BN partials ----------------
__global__ void k_lin(const float* __restrict__ QB, const float* __restrict__ LW,
                      const float* __restrict__ LB){
    extern __shared__ float sm[];
    float* post = sm;            // 64*76
    float* LWs  = sm + 4864;     // 75*76
    float* outs = sm + 4864 + 5700;  // 64*76
    float* s_amp  = sm + 4864 + 5700 + 4864;
    float* s_ampi = s_amp + 64;
    int tid = threadIdx.x;
    int n0 = blockIdx.x * 64;
    if (tid < 64){
        float a = d_amp[n0 + tid];
        s_amp[tid] = a; s_ampi[tid] = 1.0f / a;
    }
    for (int i = tid; i < 75*75; i += 256){
        int k = i / 75, j = i - k*75;
        LWs[k*76 + j] = LW[i];
    }
    __syncthreads();
    for (int i = tid; i < 64*75; i += 256){
        int nn = i / 75, j = i - nn*75;
        int t = j / 15, g = j - t*15;
        const float* rp = d_R + (size_t)(n0+nn)*240 + t*48;
        float r1 = rp[g], r2 = rp[15+g], r3 = rp[30+g];
        post[nn*76 + j] = r1 + s_amp[nn]*r2 + s_ampi[nn]*r3 + QB[j];
    }
    __syncthreads();
    if (tid < 240){
        int q = tid / 15, g5 = tid - q*15;
        int j0 = g5*5;
        float acc[4][5];
        #pragma unroll
        for (int i = 0; i < 4; i++)
            #pragma unroll
            for (int c = 0; c < 5; c++) acc[i][c] = LB[j0+c];
        for (int k = 0; k < 75; k++){
            float pv[4];
            #pragma unroll
            for (int i = 0; i < 4; i++) pv[i] = post[(q*4+i)*76 + k];
            #pragma unroll
            for (int c = 0; c < 5; c++){
                float wv = LWs[k*76 + j0 + c];
                #pragma unroll
                for (int i = 0; i < 4; i++) acc[i][c] = fmaf(pv[i], wv, acc[i][c]);
            }
        }
        #pragma unroll
        for (int i = 0; i < 4; i++){
            int nn = q*4 + i;
            #pragma unroll
            for (int c = 0; c < 5; c++){
                outs[nn*76 + j0 + c] = acc[i][c];
                d_hpre[(n0+nn)*Ff + j0 + c] = acc[i][c];
            }
        }
    }
    __syncthreads();
    if (tid < 75){
        float s = 0.f, s2 = 0.f;
        for (int nn = 0; nn < 64; nn++){
            float v = outs[nn*76 + tid];
            s += v; s2 = fmaf(v, v, s2);
        }
        d_bnp1[blockIdx.x*Ff + tid] = s;
        d_bnp2[blockIdx.x*Ff + tid] = s2;
    }
}

// grid 75, block 256: parallel deterministic tree reduction of BN partials
__global__ void k_bnred(const float* __restrict__ gamma, const float* __restrict__ beta){
    __shared__ float s1[256], s2[256];
    int j = blockIdx.x, t = threadIdx.x;
    s1[t] = d_bnp1[t*Ff + j];
    s2[t] = d_bnp2[t*Ff + j];
    __syncthreads();
    for (int d = 128; d > 0; d >>= 1){
        if (t < d){ s1[t] += s1[t+d]; s2[t] += s2[t+d]; }
        __syncthreads();
    }
    if (t == 0){
        float mu  = s1[0] / (float)Nn;
        float var = s2[0] / (float)Nn - mu*mu;
        var = fmaxf(var, 0.f);
        float sc = gamma[j] * rsqrtf(var + 1e-5f);
        d_scale[j] = sc;
        d_shift[j] = beta[j] - mu*sc;
    }
}

// ---------------- fused readout ----------------
__global__ void k_read(const int* __restrict__ batch,
                       const float* __restrict__ w1, const float* __restrict__ b1,
                       const float* __restrict__ w2, const float* __restrict__ b2,
                       const float* __restrict__ w3, const float* __restrict__ b3,
                       float* __restrict__ out){
    __shared__ float gv[Ff], h1[50], h2[25];
    __shared__ int bounds[2];
    int g = blockIdx.x, tid = threadIdx.x;
    if (tid < 2){
        int target = g + tid;
        int lo = 0, hi = Nn;
        while (lo < hi){ int mid = (lo+hi) >> 1; if (batch[mid] < target) lo = mid+1; else hi = mid; }
        bounds[tid] = lo;
    }
    __syncthreads();
    int a = bounds[0], b = bounds[1];
    for (int j = tid; j < Ff; j += blockDim.x){
        float sc = d_scale[j], sh = d_shift[j];
        float s = 0.f;
        for (int n = a; n < b; n++)
            s += fmaxf(fmaf(d_hpre[n*Ff + j], sc, sh), 0.f);
        gv[j] = s;
    }
    __syncthreads();
    if (tid < 50){
        float s = b1[tid];
        for (int k = 0; k < Ff; k++) s = fmaf(gv[k], w1[k*50 + tid], s);
        h1[tid] = fmaxf(s, 0.f);
    }
    __syncthreads();
    if (tid < 25){
        float s = b2[tid];
        for (int k = 0; k < 50; k++) s = fmaf(h1[k], w2[k*25 + tid], s);
        h2[tid] = fmaxf(s, 0.f);
    }
    __syncthreads();
    if (tid == 0){
        float s = b3[0];
        for (int k = 0; k < 25; k++) s = fmaf(h2[k], w3[k], s);
        out[g] = s;
    }
}

// ---------------- launch ----------------
extern "C" void kernel_launch(void* const* d_in, const int* in_sizes, int n_in,
                              void* d_out, int out_size){
    const int*   x     = (const int*)  d_in[0];
    const int*   ei    = (const int*)  d_in[1];
    const int*   eattr = (const int*)  d_in[2];
    const int*   batch = (const int*)  d_in[3];
    const float* nemb  = (const float*)d_in[4];
    const float* eemb  = (const float*)d_in[5];
    const float* eew   = (const float*)d_in[6];
    const float* eeb   = (const float*)d_in[7];
    const float* pw    = (const float*)d_in[8];
    const float* pb    = (const float*)d_in[9];
    const float* qw    = (const float*)d_in[10];
    const float* qb    = (const float*)d_in[11];
    const float* lw    = (const float*)d_in[12];
    const float* lb    = (const float*)d_in[13];
    const float* bng   = (const float*)d_in[14];
    const float* bnb   = (const float*)d_in[15];
    const float* w1    = (const float*)d_in[16];
    const float* b1    = (const float*)d_in[17];
    const float* w2    = (const float*)d_in[18];
    const float* b2    = (const float*)d_in[19];
    const float* w3    = (const float*)d_in[20];
    const float* b3    = (const float*)d_in[21];
    float* out = (float*)d_out;
    const int* src = ei;
    const int* dst = ei + Ee;

    cudaFuncSetAttribute(k_lin, cudaFuncAttributeMaxDynamicSharedMemorySize, 62464);

    k_inith<<<(Nn*Ff+255)/256,256>>>(x, nemb);                    // 1 (also zeroes d_cur)
    k_repack<<<dim3(1125,2),256>>>(pw, qw);                       // 2
    k_hist<<<Ee/256,256>>>(dst);                                  // 3
    // 4: SACRIFICIAL k_post2 for profiling. Reads steady-state d_AGG/d_QW3 from the
    // previous replay (identical every replay); its d_R output is fully overwritten
    // by the real k_post2(0) below. First call: d_AGG/d_QW3 zero-init -> benign.
    k_post2<<<dim3(Nn/128,5),256>>>(0);                           // 4 <- profiled slot
    k_pre<<<dim3(Nn/64,6),256>>>(0, pb);                          // 5
    k_scan<<<1,1024>>>();                                         // 6
    k_scatter<<<Ee/256,256>>>(src, dst, eattr);                   // 7
    k_sort<<<64,256>>>();                                         // 8
    k_ctab<<<16,128>>>(eemb, eew, eeb, pw);                       // 9

    for (int l = 0; l < 4; l++){
        if (l > 0)
            k_pre<<<dim3(Nn/64,6),256>>>(l, pb + l*TF);
        k_agg<<<Nn*3/8,256>>>(l);
        k_post2<<<dim3(Nn/128,5),256>>>(l);
        k_lin<<<Nn/64,256,62464>>>(qb + l*Ff, lw + l*Ff*Ff, lb + l*Ff);
        k_bnred<<<75,256>>>(bng + l*Ff, bnb + l*Ff);
    }

    k_read<<<NGR,128>>>(batch, w1, b1, w2, b2, w3, b3, out);
}

// round 11
// speedup vs baseline: 1.2481x; 1.2376x over previous
#include <cuda_runtime.h>
#include <math.h>

#define Nn 16384
#define Ee 262144
#define Tt 5
#define Ff 75
#define TF 375
#define PSTR 384
#define AGGW 1500       // Tt*300  [node][tower][mean|mn|mx|std]
#define NGR 256
#define AVG_DEG_LOG 2.8332133440562162f
typedef unsigned long long ull;

// ---------------- static scratch ----------------
static __device__ float d_h[Nn*Ff];
static __device__ float d_hpre[Nn*Ff];
static __device__ float d_A[Nn*PSTR];       // pads [375..383] stay zero
static __device__ float d_Bm[Nn*PSTR];      // pads stay zero
static __device__ float d_AGG[(size_t)Nn*AGGW];
static __device__ float d_R[(size_t)Nn*240];
static __device__ float d_amp[Nn];
static __device__ int   d_off[Nn+1];
static __device__ int   d_cur[Nn];
static __device__ int   d_edges[Ee];
static __device__ float d_Ctab[16*TF];
static __device__ float d_W2[4*75*768];
static __device__ float d_QW3[4*5*300*48];
static __device__ float d_bnp1[256*Ff];
static __device__ float d_bnp2[256*Ff];
static __device__ float d_scale[Ff];
static __device__ float d_shift[Ff];

// ---------------- f32x2 helpers ----------------
__device__ __forceinline__ ull fdup(float v){
    ull r; unsigned u = __float_as_uint(v);
    asm("mov.b64 %0, {%1,%1};" : "=l"(r) : "r"(u));
    return r;
}
__device__ __forceinline__ float2 upk(ull v){
    unsigned lo, hi;
    asm("mov.b64 {%0,%1}, %2;" : "=r"(lo), "=r"(hi) : "l"(v));
    return make_float2(__uint_as_float(lo), __uint_as_float(hi));
}
__device__ __forceinline__ ull padd(ull a, ull b){
    ull r; asm("add.rn.f32x2 %0, %1, %2;" : "=l"(r) : "l"(a), "l"(b));
    return r;
}
#define FFMA2(d,a,b) asm("fma.rn.f32x2 %0, %1, %2, %0;" : "+l"(d) : "l"(a), "l"(b))

// ---------------- precompute ----------------
__global__ void k_inith(const int* __restrict__ x, const float* __restrict__ nemb){
    int i = blockIdx.x*blockDim.x + threadIdx.x;
    if (i < Nn) d_cur[i] = 0;
    if (i >= Nn*Ff) return;
    int n = i / Ff, c = i - n*Ff;
    d_h[i] = nemb[x[n]*Ff + c];
}

__global__ void k_repack(const float* __restrict__ pw, const float* __restrict__ qw){
    int i = blockIdx.x*256 + threadIdx.x;
    if (blockIdx.y == 0){
        if (i < 4*75*768){
            int l = i / (75*768); int r = i - l*(75*768);
            int c = r / 768;      int j = r - c*768;
            float v = 0.f;
            if (j < 750){
                int isB = (j >= 375); int jj = isB ? j-375 : j;
                int t = jj/75, g = jj - t*75;
                v = pw[(((l*5 + t)*225) + (isB?75:0) + c)*75 + g];
            }
            d_W2[i] = v;
        }
    } else {
        if (i < 4*5*300*48){
            int l = i / (5*300*48); int r = i - l*(5*300*48);
            int t = r / (300*48);   r -= t*(300*48);
            int k = r / 48;         int j = r - k*48;
            float v = 0.f;
            if (j < 45){
                int part = j/15, g = j - part*15;
                v = qw[((l*5+t)*900 + part*300 + k)*15 + g];
            }
            d_QW3[i] = v;
        }
    }
}

__global__ void k_hist(const int* __restrict__ dst){
    int e = blockIdx.x*blockDim.x + threadIdx.x;
    if (e < Ee) atomicAdd(&d_cur[dst[e]], 1);
}

__global__ void k_scan(){   // 1 block, 1024 threads, 16 nodes each; also amp
    __shared__ int part[1024];
    int t = threadIdx.x;
    int loc[16]; int s = 0;
    #pragma unroll
    for (int i = 0; i < 16; i++){ loc[i] = d_cur[t*16+i]; s += loc[i]; }
    part[t] = s;
    __syncthreads();
    for (int d = 1; d < 1024; d <<= 1){
        int v = (t >= d) ? part[t-d] : 0;
        __syncthreads();
        part[t] += v;
        __syncthreads();
    }
    int run = part[t] - s;
    #pragma unroll
    for (int i = 0; i < 16; i++){
        d_off[t*16+i] = run;
        d_cur[t*16+i] = run;
        float cf = (float)(loc[i] > 0 ? loc[i] : 1);
        d_amp[t*16+i] = logf(cf + 1.0f) / AVG_DEG_LOG;
        run += loc[i];
    }
    if (t == 1023) d_off[Nn] = run;
}

__global__ void k_scatter(const int* __restrict__ src, const int* __restrict__ dst,
                          const int* __restrict__ attr){
    int e = blockIdx.x*blockDim.x + threadIdx.x;
    if (e >= Ee) return;
    int d = dst[e];
    int pos = atomicAdd(&d_cur[d], 1);
    d_edges[pos] = src[e] | (attr[e] << 16);
}

// canonical per-segment order; local-memory insertion sort (fallback for long segs)
__global__ void k_sort(){
    int n = blockIdx.x*blockDim.x + threadIdx.x;
    if (n >= Nn) return;
    int lo = d_off[n];
    int m = d_off[n+1] - lo;
    if (m <= 72){
        int a[72];
        for (int i = 0; i < m; i++) a[i] = d_edges[lo+i];
        for (int i = 1; i < m; i++){
            int key = a[i]; int j = i-1;
            while (j >= 0 && a[j] > key){ a[j+1] = a[j]; j--; }
            a[j+1] = key;
        }
        for (int i = 0; i < m; i++) d_edges[lo+i] = a[i];
    } else {
        for (int i = 1; i < m; i++){
            int key = d_edges[lo+i]; int j = i-1;
            while (j >= 0 && d_edges[lo+j] > key){ d_edges[lo+j+1] = d_edges[lo+j]; j--; }
            d_edges[lo+j+1] = key;
        }
    }
}

__global__ void k_ctab(const float* __restrict__ eemb, const float* __restrict__ eew,
                       const float* __restrict__ eeb,  const float* __restrict__ pw){
    int l = blockIdx.x >> 2, a = blockIdx.x & 3;
    __shared__ float ee[Ff];
    int tid = threadIdx.x;
    for (int f = tid; f < Ff; f += blockDim.x){
        float s = eeb[l*Ff + f];
        for (int d0 = 0; d0 < 50; d0++)
            s = fmaf(eemb[a*50 + d0], eew[(l*50 + d0)*Ff + f], s);
        ee[f] = s;
    }
    __syncthreads();
    for (int j = tid; j < TF; j += blockDim.x){
        int t = j / Ff, g = j - t*Ff;
        const float* w = pw + ((size_t)(l*Tt + t))*225*Ff + 150*Ff + g;
        float s = 0.f;
        for (int f = 0; f < Ff; f++) s = fmaf(ee[f], w[f*Ff], s);
        d_Ctab[(l*4 + a)*TF + j] = s;
    }
}

// ---------------- k_pre: GEMM tile 64n x 128j, node-paired f32x2 (verified) ----------------
__global__ __launch_bounds__(256, 4) void k_pre(int l, const float* __restrict__ PB){
    __shared__ float Hs[75*68];   // [c][nn], stride 68
    __shared__ float Ws[25*128];
    int tid = threadIdx.x;
    int tx = tid & 31, ty = tid >> 5;
    int n0 = blockIdx.x * 64;
    int chunk = blockIdx.y;       // 0..5
    const float* w2p = d_W2 + l*75*768 + chunk*128;

    for (int i = tid; i < 64*75; i += 256){
        int nn = i / 75, c = i - nn*75;
        float v;
        if (l == 0) v = d_h[(n0+nn)*Ff + c];
        else        v = fmaxf(fmaf(d_hpre[(n0+nn)*Ff + c], d_scale[c], d_shift[c]), 0.f);
        Hs[c*68 + nn] = v;
    }

    ull acc[4][4];
    #pragma unroll
    for (int m = 0; m < 4; m++)
        #pragma unroll
        for (int p = 0; p < 4; p++) acc[m][p] = 0ull;

    for (int s = 0; s < 3; s++){
        int c0 = s*25;
        __syncthreads();
        for (int i = tid; i < 25*128; i += 256){
            int kk = i >> 7, j = i & 127;
            Ws[i] = w2p[(c0+kk)*768 + j];
        }
        __syncthreads();
        #pragma unroll 5
        for (int kk = 0; kk < 25; kk++){
            const float* hr = &Hs[(c0+kk)*68 + ty*8];
            ulonglong2 h01 = *(const ulonglong2*)(hr);
            ulonglong2 h23 = *(const ulonglong2*)(hr+4);
            ull hv[4] = {h01.x, h01.y, h23.x, h23.y};
            float4 wf = *(const float4*)&Ws[kk*128 + tx*4];
            ull wd0 = fdup(wf.x), wd1 = fdup(wf.y), wd2 = fdup(wf.z), wd3 = fdup(wf.w);
            #pragma unroll
            for (int m = 0; m < 4; m++){
                FFMA2(acc[m][0], hv[m], wd0);
                FFMA2(acc[m][1], hv[m], wd1);
                FFMA2(acc[m][2], hv[m], wd2);
                FFMA2(acc[m][3], hv[m], wd3);
            }
        }
    }

    int jbase = chunk*128 + tx*4;
    #pragma unroll
    for (int m = 0; m < 4; m++){
        int na = n0 + ty*8 + 2*m;
        int nb = na + 1;
        #pragma unroll
        for (int p = 0; p < 4; p++){
            float2 v = upk(acc[m][p]);
            int j = jbase + p;
            if (j < 375){
                float bias = PB[j];
                d_A[na*PSTR + j] = v.x + bias;
                d_A[nb*PSTR + j] = v.y + bias;
            } else if (j < 750){
                int jb = j - 375;
                d_Bm[na*PSTR + jb] = v.x;
                d_Bm[nb*PSTR + jb] = v.y;
            }
        }
    }
}

// ---------------- k_agg: 3 warps/node, simple chain (round-8 verified) ----------------
__global__ __launch_bounds__(256) void k_agg(int l){
    __shared__ float ct[4*384];
    int tid = threadIdx.x;
    const float* cl = d_Ctab + l*4*TF;
    for (int i = tid; i < 4*384; i += 256){
        int a = i / 384, f = i - a*384;
        ct[i] = (f < 375) ? cl[a*375 + f] : 0.f;
    }
    __syncthreads();
    int gw = (blockIdx.x*256 + tid) >> 5;
    int node = gw / 3;
    int third = gw - node*3;
    int lane = tid & 31;
    int fbase = third*128 + lane*4;
    int o0 = d_off[node], o1 = d_off[node+1];

    ull sum0 = 0, sum1 = 0, sq0 = 0, sq1 = 0;
    float mn0 = 3.4e38f, mn1 = 3.4e38f, mn2 = 3.4e38f, mn3 = 3.4e38f;
    float mx0 = -3.4e38f, mx1 = -3.4e38f, mx2 = -3.4e38f, mx3 = -3.4e38f;

    for (int i = o0; i < o1; i++){
        int p = d_edges[i];
        ulonglong2 b = *(const ulonglong2*)(d_Bm + (p & 0xFFFF)*PSTR + fbase);
        ulonglong2 c = *(const ulonglong2*)(ct + (p >> 16)*384 + fbase);
        ull v0 = padd(b.x, c.x);
        ull v1 = padd(b.y, c.y);
        sum0 = padd(sum0, v0);
        sum1 = padd(sum1, v1);
        FFMA2(sq0, v0, v0);
        FFMA2(sq1, v1, v1);
        float2 f0 = upk(v0), f1 = upk(v1);
        mn0 = fminf(mn0, f0.x); mx0 = fmaxf(mx0, f0.x);
        mn1 = fminf(mn1, f0.y); mx1 = fmaxf(mx1, f0.y);
        mn2 = fminf(mn2, f1.x); mx2 = fmaxf(mx2, f1.x);
        mn3 = fminf(mn3, f1.y); mx3 = fmaxf(mx3, f1.y);
    }

    int cnt = o1 - o0;
    float inv = 1.0f / (float)(cnt > 0 ? cnt : 1);
    bool has = cnt > 0;
    float* aggb = d_AGG + (size_t)node*AGGW;
    float4 a4 = *(const float4*)(d_A + node*PSTR + fbase);
    float2 s0 = upk(sum0), s1 = upk(sum1);
    float2 q0 = upk(sq0),  q1 = upk(sq1);
    float av[4] = {a4.x, a4.y, a4.z, a4.w};
    float sv[4] = {s0.x, s0.y, s1.x, s1.y};
    float qv[4] = {q0.x, q0.y, q1.x, q1.y};
    float nv[4] = {mn0, mn1, mn2, mn3};
    float xv[4] = {mx0, mx1, mx2, mx3};
    #pragma unroll
    for (int e = 0; e < 4; e++){
        int f = fbase + e;
        if (f < 375){
            float mp  = sv[e]*inv;
            float var = fmaf(-mp, mp, qv[e]*inv);
            float sd  = sqrtf(fmaxf(var, 0.f) + 1e-5f);
            float a   = av[e];
            int t = f/75, ff = f - t*75;
            float* dp = aggb + t*300 + ff;
            dp[0]   = has ? a + mp    : 0.f;
            dp[75]  = has ? a + nv[e] : 0.f;
            dp[150] = has ? a + xv[e] : 0.f;
            dp[225] = sd;
        }
    }
}

// ---------------- k_post2: double-buffered per-tower GEMM [128n x 48] x [300k] ----------------
// Same math/summation order as verified version; fills are register-staged float4
// prefetches so the DRAM latency of chunk s+1 hides behind chunk s's compute.
__global__ __launch_bounds__(256, 3) void k_post2(int l){
    extern __shared__ float sm2[];
    // layout: Ag[2][20*260], Ws[2][20*48]
    float* AgB0 = sm2;
    float* AgB1 = sm2 + 5200;
    float* WsB0 = sm2 + 10400;
    float* WsB1 = sm2 + 10400 + 960;
    int tid = threadIdx.x;
    int tx = tid & 7, ty = tid >> 3;
    int n0 = blockIdx.x * 128;
    int t  = blockIdx.y;
    const float* qwp = d_QW3 + (size_t)(l*5 + t)*300*48;

    // per-thread A-stage mapping: i = tid + r*256 < 640; nn = i/5, q = i%5
    int annA[3], aqA[3]; bool avalid[3];
    #pragma unroll
    for (int r = 0; r < 3; r++){
        int i = tid + r*256;
        avalid[r] = (i < 640);
        annA[r] = i / 5;
        aqA[r]  = i - annA[r]*5;
    }
    // W-stage mapping: tid < 240; kk = tid/12, j4 = (tid%12)*4
    bool wvalid = (tid < 240);
    int wkk = tid / 12;
    int wj4 = (tid - wkk*12)*4;

    float4 rA[3]; float4 rW;

    ull acc[4][3];
    #pragma unroll
    for (int n = 0; n < 4; n++)
        #pragma unroll
        for (int p = 0; p < 3; p++) acc[n][p] = 0ull;

#define LOAD_REGS(S) do{ \
        int k0_ = (S)*20; \
        _Pragma("unroll") \
        for (int r = 0; r < 3; r++) if (avalid[r]) \
            rA[r] = *(const float4*)(d_AGG + (size_t)(n0+annA[r])*AGGW + t*300 + k0_ + aqA[r]*4); \
        if (wvalid) rW = *(const float4*)(qwp + (k0_ + wkk)*48 + wj4); \
    }while(0)

#define STS_REGS(AG, WS) do{ \
        _Pragma("unroll") \
        for (int r = 0; r < 3; r++) if (avalid[r]){ \
            float* base_ = (AG) + 2*annA[r]; \
            *(ull*)(base_ + (aqA[r]*4+0)*260) = fdup(rA[r].x); \
            *(ull*)(base_ + (aqA[r]*4+1)*260) = fdup(rA[r].y); \
            *(ull*)(base_ + (aqA[r]*4+2)*260) = fdup(rA[r].z); \
            *(ull*)(base_ + (aqA[r]*4+3)*260) = fdup(rA[r].w); \
        } \
        if (wvalid) *(float4*)((WS) + wkk*48 + wj4) = rW; \
    }while(0)

    // prologue: chunk 0 -> buf0
    LOAD_REGS(0);
    STS_REGS(AgB0, WsB0);
    __syncthreads();

    for (int s = 0; s < 15; s++){
        float* Ag = (s & 1) ? AgB1 : AgB0;
        float* Ws = (s & 1) ? WsB1 : WsB0;
        if (s < 14) LOAD_REGS(s+1);      // prefetch next chunk (latency hidden by compute)
        #pragma unroll 5
        for (int kk = 0; kk < 20; kk++){
            const float* hr = &Ag[kk*260 + ty*8];
            ulonglong2 q0 = *(const ulonglong2*)(hr);
            ulonglong2 q1 = *(const ulonglong2*)(hr+4);
            ull hv[4] = {q0.x, q0.y, q1.x, q1.y};
            const float* wr = &Ws[kk*48 + tx*6];
            ull wv[3];
            wv[0] = *(const ull*)(wr);
            wv[1] = *(const ull*)(wr+2);
            wv[2] = *(const ull*)(wr+4);
            #pragma unroll
            for (int n = 0; n < 4; n++)
                #pragma unroll
                for (int p = 0; p < 3; p++)
                    FFMA2(acc[n][p], hv[n], wv[p]);
        }
        if (s < 14){
            __syncthreads();             // all threads done reading buf[1-cur]
            float* AgN = (s & 1) ? AgB0 : AgB1;
            float* WsN = (s & 1) ? WsB0 : WsB1;
            STS_REGS(AgN, WsN);
            __syncthreads();
        }
    }
#undef LOAD_REGS
#undef STS_REGS

    #pragma unroll
    for (int n = 0; n < 4; n++){
        int node = n0 + ty*4 + n;
        ull* dst = (ull*)&d_R[(size_t)node*240 + t*48 + tx*6];
        dst[0] = acc[n][0]; dst[1] = acc[n][1]; dst[2] = acc[n][2];
    }
}

// ---------------- k_lin: combine(amp) + 75x75 GEMM + BN partials ----------------
__global__ void k_lin(const float* __restrict__ QB, const float* __restrict__ LW,
                      const float* __restrict__ LB){
    extern __shared__ float sm[];
    float* post = sm;            // 64*76
    float* LWs  = sm + 4864;     // 75*76
    float* outs = sm + 4864 + 5700;  // 64*76
    float* s_amp  = sm + 4864 + 5700 + 4864;
    float* s_ampi = s_amp + 64;
    int tid = threadIdx.x;
    int n0 = blockIdx.x * 64;
    if (tid < 64){
        float a = d_amp[n0 + tid];
        s_amp[tid] = a; s_ampi[tid] = 1.0f / a;
    }
    for (int i = tid; i < 75*75; i += 256){
        int k = i / 75, j = i - k*75;
        LWs[k*76 + j] = LW[i];
    }
    __syncthreads();
    for (int i = tid; i < 64*75; i += 256){
        int nn = i / 75, j = i - nn*75;
        int t = j / 15, g = j - t*15;
        const float* rp = d_R + (size_t)(n0+nn)*240 + t*48;
        float r1 = rp[g], r2 = rp[15+g], r3 = rp[30+g];
        post[nn*76 + j] = r1 + s_amp[nn]*r2 + s_ampi[nn]*r3 + QB[j];
    }
    __syncthreads();
    if (tid < 240){
        int q = tid / 15, g5 = tid - q*15;
        int j0 = g5*5;
        float acc[4][5];
        #pragma unroll
        for (int i = 0; i < 4; i++)
            #pragma unroll
            for (int c = 0; c < 5; c++) acc[i][c] = LB[j0+c];
        for (int k = 0; k < 75; k++){
            float pv[4];
            #pragma unroll
            for (int i = 0; i < 4; i++) pv[i] = post[(q*4+i)*76 + k];
            #pragma unroll
            for (int c = 0; c < 5; c++){
                float wv = LWs[k*76 + j0 + c];
                #pragma unroll
                for (int i = 0; i < 4; i++) acc[i][c] = fmaf(pv[i], wv, acc[i][c]);
            }
        }
        #pragma unroll
        for (int i = 0; i < 4; i++){
            int nn = q*4 + i;
            #pragma unroll
            for (int c = 0; c < 5; c++){
                outs[nn*76 + j0 + c] = acc[i][c];
                d_hpre[(n0+nn)*Ff + j0 + c] = acc[i][c];
            }
        }
    }
    __syncthreads();
    if (tid < 75){
        float s = 0.f, s2 = 0.f;
        for (int nn = 0; nn < 64; nn++){
            float v = outs[nn*76 + tid];
            s += v; s2 = fmaf(v, v, s2);
        }
        d_bnp1[blockIdx.x*Ff + tid] = s;
        d_bnp2[blockIdx.x*Ff + tid] = s2;
    }
}

// grid 75, block 256: parallel deterministic tree reduction of BN partials
__global__ void k_bnred(const float* __restrict__ gamma, const float* __restrict__ beta){
    __shared__ float s1[256], s2[256];
    int j = blockIdx.x, t = threadIdx.x;
    s1[t] = d_bnp1[t*Ff + j];
    s2[t] = d_bnp2[t*Ff + j];
    __syncthreads();
    for (int d = 128; d > 0; d >>= 1){
        if (t < d){ s1[t] += s1[t+d]; s2[t] += s2[t+d]; }
        __syncthreads();
    }
    if (t == 0){
        float mu  = s1[0] / (float)Nn;
        float var = s2[0] / (float)Nn - mu*mu;
        var = fmaxf(var, 0.f);
        float sc = gamma[j] * rsqrtf(var + 1e-5f);
        d_scale[j] = sc;
        d_shift[j] = beta[j] - mu*sc;
    }
}

// ---------------- fused readout ----------------
__global__ void k_read(const int* __restrict__ batch,
                       const float* __restrict__ w1, const float* __restrict__ b1,
                       const float* __restrict__ w2, const float* __restrict__ b2,
                       const float* __restrict__ w3, const float* __restrict__ b3,
                       float* __restrict__ out){
    __shared__ float gv[Ff], h1[50], h2[25];
    __shared__ int bounds[2];
    int g = blockIdx.x, tid = threadIdx.x;
    if (tid < 2){
        int target = g + tid;
        int lo = 0, hi = Nn;
        while (lo < hi){ int mid = (lo+hi) >> 1; if (batch[mid] < target) lo = mid+1; else hi = mid; }
        bounds[tid] = lo;
    }
    __syncthreads();
    int a = bounds[0], b = bounds[1];
    for (int j = tid; j < Ff; j += blockDim.x){
        float sc = d_scale[j], sh = d_shift[j];
        float s = 0.f;
        for (int n = a; n < b; n++)
            s += fmaxf(fmaf(d_hpre[n*Ff + j], sc, sh), 0.f);
        gv[j] = s;
    }
    __syncthreads();
    if (tid < 50){
        float s = b1[tid];
        for (int k = 0; k < Ff; k++) s = fmaf(gv[k], w1[k*50 + tid], s);
        h1[tid] = fmaxf(s, 0.f);
    }
    __syncthreads();
    if (tid < 25){
        float s = b2[tid];
        for (int k = 0; k < 50; k++) s = fmaf(h1[k], w2[k*25 + tid], s);
        h2[tid] = fmaxf(s, 0.f);
    }
    __syncthreads();
    if (tid == 0){
        float s = b3[0];
        for (int k = 0; k < 25; k++) s = fmaf(h2[k], w3[k], s);
        out[g] = s;
    }
}

// ---------------- launch ----------------
extern "C" void kernel_launch(void* const* d_in, const int* in_sizes, int n_in,
                              void* d_out, int out_size){
    const int*   x     = (const int*)  d_in[0];
    const int*   ei    = (const int*)  d_in[1];
    const int*   eattr = (const int*)  d_in[2];
    const int*   batch = (const int*)  d_in[3];
    const float* nemb  = (const float*)d_in[4];
    const float* eemb  = (const float*)d_in[5];
    const float* eew   = (const float*)d_in[6];
    const float* eeb   = (const float*)d_in[7];
    const float* pw    = (const float*)d_in[8];
    const float* pb    = (const float*)d_in[9];
    const float* qw    = (const float*)d_in[10];
    const float* qb    = (const float*)d_in[11];
    const float* lw    = (const float*)d_in[12];
    const float* lb    = (const float*)d_in[13];
    const float* bng   = (const float*)d_in[14];
    const float* bnb   = (const float*)d_in[15];
    const float* w1    = (const float*)d_in[16];
    const float* b1    = (const float*)d_in[17];
    const float* w2    = (const float*)d_in[18];
    const float* b2    = (const float*)d_in[19];
    const float* w3    = (const float*)d_in[20];
    const float* b3    = (const float*)d_in[21];
    float* out = (float*)d_out;
    const int* src = ei;
    const int* dst = ei + Ee;

    cudaFuncSetAttribute(k_lin, cudaFuncAttributeMaxDynamicSharedMemorySize, 62464);
    cudaFuncSetAttribute(k_post2, cudaFuncAttributeMaxDynamicSharedMemorySize, 49280);

    k_inith<<<(Nn*Ff+255)/256,256>>>(x, nemb);                    // 1 (also zeroes d_cur)
    k_repack<<<dim3(1125,2),256>>>(pw, qw);                       // 2
    k_hist<<<Ee/256,256>>>(dst);                                  // 3
    k_pre<<<dim3(Nn/64,6),256>>>(0, pb);                          // 4  <- profiled slot (sanity)
    k_scan<<<1,1024>>>();                                         // 5
    k_scatter<<<Ee/256,256>>>(src, dst, eattr);                   // 6
    k_sort<<<64,256>>>();                                         // 7
    k_ctab<<<16,128>>>(eemb, eew, eeb, pw);                       // 8

    for (int l = 0; l < 4; l++){
        if (l > 0)
            k_pre<<<dim3(Nn/64,6),256>>>(l, pb + l*TF);
        k_agg<<<Nn*3/8,256>>>(l);
        k_post2<<<dim3(Nn/128,5),256,49280>>>(l);
        k_lin<<<Nn/64,256,62464>>>(qb + l*Ff, lw + l*Ff*Ff, lb + l*Ff);
        k_bnred<<<75,256>>>(bng + l*Ff, bnb + l*Ff);
    }

    k_read<<<NGR,128>>>(batch, w1, b1, w2, b2, w3, b3, out);
}